// round 12
// baseline (speedup 1.0000x reference)
#include <cuda_runtime.h>
#include <cuda_fp16.h>
#include <cstdint>

#define TSEQ 2048
#define NB   4
#define NH   8
#define HIDD 1024
#define MROWS (NB*TSEQ)   // 8192

#define XF4 2097152
#define WF4 1310720

// ---------------- scratch (device globals; no allocations allowed) ----------
__device__ float g_P [MROWS*4096];
__device__ float g_Qc[MROWS*512];
__device__ float g_Kc[MROWS*512];
__device__ float g_Vc[MROWS*1024];
__device__ float g_Bt[MROWS*8];
__device__ float g_O [MROWS*1024];

__device__ __half g_Xh[MROWS*1024];
__device__ __half g_Oh[MROWS*1024];
#define WOFF_O 4194304
__device__ __half g_Wh[5242880];

// ---------------- PTX helpers (sm_80-class only; compute_103-safe) ----------
static __device__ __forceinline__ uint32_t smem_u32(const void* p) {
    uint32_t a;
    asm("{ .reg .u64 t; cvta.to.shared.u64 t, %1; cvt.u32.u64 %0, t; }"
        : "=r"(a) : "l"(p));
    return a;
}

#define LDSM4(r, a)                                                             \
    asm volatile("ldmatrix.sync.aligned.m8n8.x4.shared.b16 {%0,%1,%2,%3}, [%4];"\
        : "=r"((r)[0]), "=r"((r)[1]), "=r"((r)[2]), "=r"((r)[3]) : "r"(a))

#define MMA16816(d, a, b0, b1)                                                  \
    asm volatile(                                                               \
        "mma.sync.aligned.m16n8k16.row.col.f32.f16.f16.f32 "                    \
        "{%0,%1,%2,%3},{%4,%5,%6,%7},{%8,%9},{%0,%1,%2,%3};"                    \
        : "+f"((d)[0]), "+f"((d)[1]), "+f"((d)[2]), "+f"((d)[3])                \
        : "r"((a)[0]), "r"((a)[1]), "r"((a)[2]), "r"((a)[3]), "r"(b0), "r"(b1))

#define CPA16(dst, src)                                                         \
    asm volatile("cp.async.cg.shared.global [%0], [%1], 16;"                    \
        :: "r"(dst), "l"(src) : "memory")
#define CPA4(dst, src)                                                          \
    asm volatile("cp.async.ca.shared.global [%0], [%1], 4;"                     \
        :: "r"(dst), "l"(src) : "memory")

// ---------------- prep: x -> fp16 and all 6 weights -> fp16 (one launch) ----
__global__ __launch_bounds__(256) void prep_fp16(
    const float* __restrict__ x,
    const float* __restrict__ Wq, const float* __restrict__ Wk,
    const float* __restrict__ Wv, const float* __restrict__ Wa,
    const float* __restrict__ Wg, const float* __restrict__ Wo,
    __half* __restrict__ Xh, __half* __restrict__ Wh)
{
    const int i = blockIdx.x * 256 + threadIdx.x;
    if (i < XF4) {
        const float4 v = ((const float4*)x)[i];
        __half2 H0; H0.x = __float2half_rn(v.x); H0.y = __float2half_rn(v.y);
        __half2 H1; H1.x = __float2half_rn(v.z); H1.y = __float2half_rn(v.w);
        *(__half2*)(Xh + (size_t)i * 4)     = H0;
        *(__half2*)(Xh + (size_t)i * 4 + 2) = H1;
        return;
    }
    const int j = i - XF4;
    if (j >= WF4) return;
    const float* src; int base;
    if (j < 262144)      { if (j < 131072) { src = Wq; base = 0; }
                           else            { src = Wk; base = 131072; } }
    else if (j < 786432) { if (j < 524288) { src = Wv; base = 262144; }
                           else            { src = Wa; base = 524288; } }
    else                 { if (j < 1048576){ src = Wg; base = 786432; }
                           else            { src = Wo; base = 1048576; } }
    const float4 v = ((const float4*)src)[j - base];
    __half2 H0; H0.x = __float2half_rn(v.x); H0.y = __float2half_rn(v.y);
    __half2 H1; H1.x = __float2half_rn(v.z); H1.y = __float2half_rn(v.w);
    *(__half2*)(Wh + (size_t)j * 4)     = H0;
    *(__half2*)(Wh + (size_t)j * 4 + 2) = H1;
}

// ------- HMMA GEMM: C = A @ B^T, fp16 inputs, fp32 accum -------------------
#define STGB  20480u
#define GSMEM (3*20480)

__global__ __launch_bounds__(256, 2) void gemm_hmma(
    const __half* __restrict__ Ah, const __half* __restrict__ Bh,
    const float* __restrict__ bias, float* __restrict__ C, int Nt,
    int bias_lo, int bias_hi, int act_lo)
{
    extern __shared__ char smc[];
    const uint32_t sb = smem_u32(smc);
    const int tid = threadIdx.x;
    const int l   = tid & 31, wid = tid >> 5;
    const int wm  = wid & 1, wn = wid >> 1;
    const int m0  = blockIdx.y << 7, n0 = blockIdx.x << 7;
    const int grp = l >> 3;

    const bool act  = (n0 >= act_lo);
    const bool hasb = bias && (n0 >= bias_lo) && (n0 < bias_hi);

    const uint32_t a_off = (uint32_t)((wm*64 + (grp & 1)*8 + (l & 7)) * 80
                                      + (grp >> 1) * 16);
    const uint32_t b_off = (uint32_t)((wn*32 + (grp >> 1)*8 + (l & 7)) * 80
                                      + (grp & 1) * 16);

    const __half* s0 = Ah + (size_t)m0 * 1024;
    const __half* s1 = Bh + (size_t)n0 * 1024;

    float acc[4][4][4];
#pragma unroll
    for (int mt = 0; mt < 4; mt++)
#pragma unroll
        for (int nt = 0; nt < 4; nt++)
#pragma unroll
            for (int r = 0; r < 4; r++) acc[mt][nt][r] = 0.f;

#define LOAD_BUF(buf, k0) do {                                                  \
    const uint32_t bb_ = sb + (uint32_t)(buf) * STGB;                           \
    const __half* ss_[2] = { s0, s1 };                                          \
    _Pragma("unroll")                                                           \
    for (int t2 = 0; t2 < 2; t2++) {                                            \
        _Pragma("unroll")                                                       \
        for (int it = 0; it < 2; it++) {                                        \
            const int idx_ = it * 256 + tid;                                    \
            const int row_ = idx_ >> 2, ch_ = idx_ & 3;                         \
            const uint32_t dst_ = bb_ + t2 * 10240u + row_ * 80u + ch_ * 16u;   \
            const __half* src_ = ss_[t2] + (size_t)row_ * 1024 + (k0) + ch_ * 8;\
            CPA16(dst_, src_);                                                  \
        }                                                                       \
    }                                                                           \
    asm volatile("cp.async.commit_group;" ::: "memory");                        \
} while (0)

#define MMAPASS(af, bf) do {                                                    \
    _Pragma("unroll")                                                           \
    for (int mt = 0; mt < 4; mt++)                                              \
        _Pragma("unroll")                                                       \
        for (int nt = 0; nt < 4; nt++)                                          \
            MMA16816(acc[mt][nt], (af) + 4*mt,                                  \
                     (bf)[(nt >> 1)*4 + (nt & 1)*2],                            \
                     (bf)[(nt >> 1)*4 + (nt & 1)*2 + 1]);                       \
} while (0)

    LOAD_BUF(0, 0);
    LOAD_BUF(1, 32);

    for (int c = 0; c < 32; c++) {
        if (c + 1 < 32)
            asm volatile("cp.async.wait_group 1;" ::: "memory");
        else
            asm volatile("cp.async.wait_group 0;" ::: "memory");
        __syncthreads();
        const uint32_t bb = sb + (uint32_t)(c % 3) * STGB;

        uint32_t a0[16], a1[16], b0[8], b1[8];
#pragma unroll
        for (int np = 0; np < 2; np++)
            LDSM4(b0 + 4*np, bb + 10240u + b_off + np * 1280u);
#pragma unroll
        for (int mt = 0; mt < 4; mt++)
            LDSM4(a0 + 4*mt, bb + a_off + mt * 1280u);

        MMAPASS(a0, b0);

        if (c + 2 < 32) LOAD_BUF((c + 2) % 3, (c + 2) * 32);

#pragma unroll
        for (int np = 0; np < 2; np++)
            LDSM4(b1 + 4*np, bb + 10240u + b_off + np * 1280u + 32u);
#pragma unroll
        for (int mt = 0; mt < 4; mt++)
            LDSM4(a1 + 4*mt, bb + a_off + mt * 1280u + 32u);

        MMAPASS(a1, b1);
    }

    const int r0 = l >> 2, c0 = (l & 3) * 2;
#pragma unroll
    for (int mt = 0; mt < 4; mt++) {
        const int row = m0 + wm*64 + mt*16 + r0;
#pragma unroll
        for (int nt = 0; nt < 4; nt++) {
            const int col = n0 + wn*32 + nt*8 + c0;
            float b0v = 0.f, b1v = 0.f;
            if (hasb) { b0v = bias[col - bias_lo]; b1v = bias[col + 1 - bias_lo]; }
            float v00 = acc[mt][nt][0] + b0v;
            float v01 = acc[mt][nt][1] + b1v;
            float v10 = acc[mt][nt][2] + b0v;
            float v11 = acc[mt][nt][3] + b1v;
            if (act) {
                v00 = 1.f / (1.f + __expf(-v00));
                v01 = 1.f / (1.f + __expf(-v01));
                v10 = 1.f / (1.f + __expf(-v10));
                v11 = 1.f / (1.f + __expf(-v11));
            }
            float2 p0; p0.x = v00; p0.y = v01;
            float2 p1; p1.x = v10; p1.y = v11;
            *(float2*)(C + (size_t)row * Nt + col)       = p0;
            *(float2*)(C + (size_t)(row + 8) * Nt + col) = p1;
        }
    }
}

// ------ fused depthwise causal conv (K=4)+silu AND beta projection ----------
#define CONVBLK 16384

__global__ __launch_bounds__(256) void conv_beta(
    const float* __restrict__ P, const float* __restrict__ x,
    const float* __restrict__ qw, const float* __restrict__ qb,
    const float* __restrict__ kw, const float* __restrict__ kb2,
    const float* __restrict__ vw, const float* __restrict__ vb2,
    const float* __restrict__ Wb, const float* __restrict__ bb,
    float* __restrict__ Qc, float* __restrict__ Kc, float* __restrict__ Vc,
    float* __restrict__ Bt)
{
    if (blockIdx.x >= CONVBLK) {
        const int m = blockIdx.x - CONVBLK;
        const int w = threadIdx.x >> 5;
        const int lane = threadIdx.x & 31;
        const float* xr = x  + (size_t)m * HIDD;
        const float* wr = Wb + (size_t)w * HIDD;
        float s = 0.f;
#pragma unroll
        for (int k = lane * 4; k < HIDD; k += 128) {
            float4 xv = *(const float4*)(xr + k);
            float4 wv = *(const float4*)(wr + k);
            s += xv.x*wv.x + xv.y*wv.y + xv.z*wv.z + xv.w*wv.w;
        }
#pragma unroll
        for (int o = 16; o; o >>= 1) s += __shfl_xor_sync(0xffffffffu, s, o);
        if (lane == 0) Bt[m*8 + w] = 1.f / (1.f + __expf(-(s + bb[w])));
        return;
    }

    const int idx = blockIdx.x * 256 + threadIdx.x;
    const int ch = idx & 2047;
    const int g  = idx >> 11;
    const int m0 = g * 4;
    const int t0 = m0 & (TSEQ - 1);

    const float* wc; float bias0, scale; float* outp; int outC, oc;
    if (ch < 512)       { wc = qw + ch*4;        bias0 = qb[ch];        scale = 1.f;
                          outp = Qc; outC = 512;  oc = ch; }
    else if (ch < 1024) { const int c2 = ch-512; wc = kw + c2*4; bias0 = kb2[c2];
                          scale = 0.125f; outp = Kc; outC = 512; oc = c2; }
    else                { const int c2 = ch-1024; wc = vw + c2*4; bias0 = vb2[c2];
                          scale = 1.f; outp = Vc; outC = 1024; oc = c2; }

    const float* in = P + ch;
    float xv[7];
#pragma unroll
    for (int j = 0; j < 7; j++)
        xv[j] = (t0 - 3 + j >= 0) ? in[(size_t)(m0 - 3 + j) * 4096] : 0.f;

    const float w0 = wc[0], w1 = wc[1], w2 = wc[2], w3 = wc[3];
#pragma unroll
    for (int i = 0; i < 4; i++) {
        float a = bias0;
        a = fmaf(w0, xv[i],   a);
        a = fmaf(w1, xv[i+1], a);
        a = fmaf(w2, xv[i+2], a);
        a = fmaf(w3, xv[i+3], a);
        const float s = a * (1.f / (1.f + __expf(-a)));
        outp[(size_t)(m0 + i) * outC + oc] = s * scale;
    }
}

// ---------------- gated delta-rule recurrence (chunked cp.async) ------------
// grid (B*H, 16), block 64: 8 threads per v-column (8 columns/block).
// Thread q_ owns k/S elements {8*q_ .. 8*q_+7} (two float4s).
#define DCH 16

__global__ __launch_bounds__(64) void delta_recurrence(
    const float* __restrict__ Qc, const float* __restrict__ Kc,
    const float* __restrict__ Vc, const float* __restrict__ P,
    const float* __restrict__ Bt, float* __restrict__ O)
{
    const int bh = blockIdx.x;
    const int b = bh >> 3, h = bh & 7;
    const int tid = threadIdx.x;
    const int q_  = tid & 7;                    // element-range owner 0..7
    const int col = tid >> 3;                   // column 0..7

    __shared__ __align__(16) float sk[2][DCH][72];
    __shared__ __align__(16) float sq[2][DCH][72];
    __shared__ __align__(16) float sv[2][DCH][8];
    __shared__ __align__(16) float sa[2][DCH][8];
    __shared__ __align__(16) float sbe[2][DCH];

    const uint32_t skb = smem_u32(sk);
    const uint32_t sqb = smem_u32(sq);
    const uint32_t svb = smem_u32(sv);
    const uint32_t sab = smem_u32(sa);
    const uint32_t sbb = smem_u32(sbe);

    float S[8];
#pragma unroll
    for (int i = 0; i < 8; i++) S[i] = 0.f;

    const float* kb  = Kc + (size_t)b * TSEQ * 512  + h * 64;
    const float* qb  = Qc + (size_t)b * TSEQ * 512  + h * 64;
    const float* vb  = Vc + (size_t)b * TSEQ * 1024 + h * 128 + blockIdx.y * 8;
    const float* ab  = P  + (size_t)b * TSEQ * 4096 + 2048 + h * 128 + blockIdx.y * 8;
    const float* bbp = Bt + (size_t)b * TSEQ * 8    + h;
    float*       ob  = O  + (size_t)b * TSEQ * 1024 + h * 128 + blockIdx.y * 8 + col;

#define DSTAGE(buf, t0) do {                                                    \
    _Pragma("unroll")                                                           \
    for (int i = 0; i < 4; i++) {                                               \
        const int idx = i * 64 + tid;                                           \
        const int row = idx >> 4, seg = idx & 15;                               \
        CPA16(skb + (uint32_t)(buf) * (DCH*72*4) + row * 288u + seg * 16u,      \
              kb + (size_t)((t0) + row) * 512 + seg * 4);                       \
        CPA16(sqb + (uint32_t)(buf) * (DCH*72*4) + row * 288u + seg * 16u,      \
              qb + (size_t)((t0) + row) * 512 + seg * 4);                       \
    }                                                                           \
    if (tid < 32) {                                                             \
        const int row = tid >> 1, seg = tid & 1;                                \
        CPA16(svb + (uint32_t)(buf) * (DCH*8*4) + row * 32u + seg * 16u,        \
              vb + (size_t)((t0) + row) * 1024 + seg * 4);                      \
        CPA16(sab + (uint32_t)(buf) * (DCH*8*4) + row * 32u + seg * 16u,        \
              ab + (size_t)((t0) + row) * 4096 + seg * 4);                      \
    }                                                                           \
    if (tid < DCH)                                                              \
        CPA4(sbb + (uint32_t)(buf) * (DCH*4) + tid * 4u,                        \
             bbp + (size_t)((t0) + tid) * 8);                                   \
    asm volatile("cp.async.commit_group;" ::: "memory");                        \
} while (0)

    DSTAGE(0, 0);

    const int NCHUNK = TSEQ / DCH;
    for (int c = 0; c < NCHUNK; c++) {
        if (c + 1 < NCHUNK) {
            DSTAGE((c + 1) & 1, (c + 1) * DCH);
            asm volatile("cp.async.wait_group 1;" ::: "memory");
        } else {
            asm volatile("cp.async.wait_group 0;" ::: "memory");
        }
        __syncthreads();
        const int buf = c & 1;

#pragma unroll 4
        for (int t = 0; t < DCH; t++) {
            const float4* k4 = (const float4*)&sk[buf][t][0];
            const float4* q4 = (const float4*)&sq[buf][t][0];
            const float be_c = sbe[buf][t];
            const float v_c  = sv[buf][t][col];
            const float a_c  = sa[buf][t][col];

            const float4 kA = k4[2*q_], kB = k4[2*q_ + 1];
            const float4 qA = q4[2*q_], qB = q4[2*q_ + 1];

            float d0, d1, d2, d3;
            d0 = kA.x * S[0];
            d1 = kA.y * S[1];
            d2 = kA.z * S[2];
            d3 = kA.w * S[3];
            d0 = fmaf(kB.x, S[4], d0);
            d1 = fmaf(kB.y, S[5], d1);
            d2 = fmaf(kB.z, S[6], d2);
            d3 = fmaf(kB.w, S[7], d3);
            float rd = (d0 + d1) + (d2 + d3);
            rd += __shfl_xor_sync(0xffffffffu, rd, 1);
            rd += __shfl_xor_sync(0xffffffffu, rd, 2);
            rd += __shfl_xor_sync(0xffffffffu, rd, 4);
            const float ncc = be_c * (v_c - rd);

            S[0] = fmaf(a_c, S[0], ncc * kA.x);
            S[1] = fmaf(a_c, S[1], ncc * kA.y);
            S[2] = fmaf(a_c, S[2], ncc * kA.z);
            S[3] = fmaf(a_c, S[3], ncc * kA.w);
            S[4] = fmaf(a_c, S[4], ncc * kB.x);
            S[5] = fmaf(a_c, S[5], ncc * kB.y);
            S[6] = fmaf(a_c, S[6], ncc * kB.z);
            S[7] = fmaf(a_c, S[7], ncc * kB.w);

            float o0, o1, o2, o3;
            o0 = qA.x * S[0];
            o1 = qA.y * S[1];
            o2 = qA.z * S[2];
            o3 = qA.w * S[3];
            o0 = fmaf(qB.x, S[4], o0);
            o1 = fmaf(qB.y, S[5], o1);
            o2 = fmaf(qB.z, S[6], o2);
            o3 = fmaf(qB.w, S[7], o3);
            float oo = (o0 + o1) + (o2 + o3);
            oo += __shfl_xor_sync(0xffffffffu, oo, 1);
            oo += __shfl_xor_sync(0xffffffffu, oo, 2);
            oo += __shfl_xor_sync(0xffffffffu, oo, 4);
            if (q_ == 0) ob[(size_t)(c * DCH + t) * 1024] = oo;
        }
        __syncthreads();
    }
}

// -------- LayerNorm over DV + sigmoid-gate multiply + fp16 convert ----------
__global__ __launch_bounds__(256) void ln_gate_fp16(
    const float* __restrict__ O, const float* __restrict__ P,
    const float* __restrict__ lnw, const float* __restrict__ lnb,
    __half* __restrict__ hi)
{
    const int g = blockIdx.x * 8 + (threadIdx.x >> 5);
    const int lane = threadIdx.x & 31;
    const int m = g >> 3, h = g & 7;
    const float* row  = O + (size_t)m * 1024 + h * 128;
    const float* grow = P + (size_t)m * 4096 + 3072 + h * 128;

    float xs[4];
    float sum = 0.f;
#pragma unroll
    for (int i = 0; i < 4; i++) { xs[i] = row[lane + 32*i]; sum += xs[i]; }
#pragma unroll
    for (int o = 16; o; o >>= 1) sum += __shfl_xor_sync(0xffffffffu, sum, o);
    const float mu = sum * (1.f / 128.f);

    float vs = 0.f;
#pragma unroll
    for (int i = 0; i < 4; i++) { const float d = xs[i] - mu; vs = fmaf(d, d, vs); }
#pragma unroll
    for (int o = 16; o; o >>= 1) vs += __shfl_xor_sync(0xffffffffu, vs, o);
    const float rstd = rsqrtf(vs * (1.f / 128.f) + 1e-5f);

#pragma unroll
    for (int i = 0; i < 4; i++) {
        const int c = lane + 32*i;
        const float val = ((xs[i] - mu) * rstd * lnw[c] + lnb[c]) * grow[c];
        hi[(size_t)m * 1024 + h * 128 + c] = __float2half_rn(val);
    }
}

// ---------------- launch ----------------------------------------------------
extern "C" void kernel_launch(void* const* d_in, const int* in_sizes, int n_in,
                              void* d_out, int out_size)
{
    const float* x   = (const float*)d_in[0];
    const float* Wq  = (const float*)d_in[1];
    const float* Wk  = (const float*)d_in[2];
    const float* Wv  = (const float*)d_in[3];
    const float* Wa  = (const float*)d_in[4];
    const float* ba  = (const float*)d_in[5];
    const float* Wb  = (const float*)d_in[6];
    const float* bbv = (const float*)d_in[7];
    const float* Wg  = (const float*)d_in[8];
    const float* Wo  = (const float*)d_in[9];
    const float* qcw = (const float*)d_in[10];
    const float* qcb = (const float*)d_in[11];
    const float* kcw = (const float*)d_in[12];
    const float* kcb = (const float*)d_in[13];
    const float* vcw = (const float*)d_in[14];
    const float* vcb = (const float*)d_in[15];
    const float* lnw = (const float*)d_in[16];
    const float* lnb = (const float*)d_in[17];
    float* outp = (float*)d_out;

    float *P, *Qc, *Kc, *Vc, *Bt, *O;
    __half *Xh, *Oh, *Wh;
    cudaGetSymbolAddress((void**)&P,  g_P);
    cudaGetSymbolAddress((void**)&Qc, g_Qc);
    cudaGetSymbolAddress((void**)&Kc, g_Kc);
    cudaGetSymbolAddress((void**)&Vc, g_Vc);
    cudaGetSymbolAddress((void**)&Bt, g_Bt);
    cudaGetSymbolAddress((void**)&O,  g_O);
    cudaGetSymbolAddress((void**)&Xh, g_Xh);
    cudaGetSymbolAddress((void**)&Oh, g_Oh);
    cudaGetSymbolAddress((void**)&Wh, g_Wh);

    cudaFuncSetAttribute(gemm_hmma, cudaFuncAttributeMaxDynamicSharedMemorySize, GSMEM);

    // 0: prep (x + all weights -> fp16)
    prep_fp16<<<(XF4 + WF4 + 255)/256, 256>>>(
        x, Wq, Wk, Wv, Wa, Wg, Wo, Xh, Wh);

    // 1: ONE fused projection GEMM (Q|K|V|A|G), N=4096
    gemm_hmma<<<dim3(32, 64), 256, GSMEM>>>(
        Xh, Wh, ba, P, 4096,
        /*bias_lo=*/2048, /*bias_hi=*/3072, /*act_lo=*/2048);

    // 2: conv+silu (Q,K,V) fused with beta projection
    conv_beta<<<CONVBLK + MROWS, 256>>>(
        P, x, qcw, qcb, kcw, kcb, vcw, vcb, Wb, bbv, Qc, Kc, Vc, Bt);

    // 3: sequential gated delta-rule scan (8 threads/column, 1024 warps)
    delta_recurrence<<<dim3(NB*NH, 16), 64>>>(Qc, Kc, Vc, P, Bt, O);

    // 4: LN + gate + fp16 convert; 5: output projection
    ln_gate_fp16<<<MROWS, 256>>>(O, P, lnw, lnb, Oh);
    gemm_hmma<<<dim3(8, 64), 256, GSMEM>>>(
        Oh, Wh + WOFF_O, nullptr, outp, 1024,
        /*bias_lo=*/0, /*bias_hi=*/0, /*act_lo=*/1 << 30);
}